// round 1
// baseline (speedup 1.0000x reference)
#include <cuda_runtime.h>
#include <cuda_bf16.h>

// BPMLL loss, fused single-launch:
//   s = sigmoid(c); pos_i = sum_k y_ik * exp(-s_ik); neg_i = sum_k (1-y_ik) * exp(s_ik)
//   out = mean_i( pos_i * neg_i / (|Y_i| * (512 - |Y_i|)) )
//
// 512 blocks (one per row) x 256 threads (float2 per thread covers the 512-wide row).
// Last-block-done pattern (threadfence + atomic counter, counter reset by the last
// block) performs the final mean in the same launch. Scratch in __device__ globals.

#define ROWS 512
#define COLS 512
#define TPB  256

__device__ float        g_partial[ROWS];
__device__ unsigned int g_count = 0;

__global__ __launch_bounds__(TPB) void bpmll_kernel(const float* __restrict__ c,
                                                    const int*   __restrict__ y,
                                                    float* __restrict__ out) {
    const int row = blockIdx.x;
    const int tid = threadIdx.x;

    // Each thread loads 2 contiguous elements of its row.
    const float2 cv = reinterpret_cast<const float2*>(c + (size_t)row * COLS)[tid];
    const int2   yv = reinterpret_cast<const int2*>(y + (size_t)row * COLS)[tid];

    float pos = 0.0f, neg = 0.0f;
    int   ys  = 0;

    {
        float s = __fdividef(1.0f, 1.0f + __expf(-cv.x));
        if (yv.x) { pos += __expf(-s); ys++; } else { neg += __expf(s); }
    }
    {
        float s = __fdividef(1.0f, 1.0f + __expf(-cv.y));
        if (yv.y) { pos += __expf(-s); ys++; } else { neg += __expf(s); }
    }

    // Warp reduction
    #pragma unroll
    for (int o = 16; o > 0; o >>= 1) {
        pos += __shfl_down_sync(0xFFFFFFFFu, pos, o);
        neg += __shfl_down_sync(0xFFFFFFFFu, neg, o);
        ys  += __shfl_down_sync(0xFFFFFFFFu, ys,  o);
    }

    __shared__ float sp[TPB / 32];
    __shared__ float sn[TPB / 32];
    __shared__ int   sy[TPB / 32];
    const int lane = tid & 31, warp = tid >> 5;
    if (lane == 0) { sp[warp] = pos; sn[warp] = neg; sy[warp] = ys; }
    __syncthreads();

    __shared__ bool is_last;
    if (tid == 0) {
        float P = 0.0f, N = 0.0f; int Y = 0;
        #pragma unroll
        for (int i = 0; i < TPB / 32; i++) { P += sp[i]; N += sn[i]; Y += sy[i]; }
        const float yn  = (float)Y;
        const float ybn = (float)(COLS - Y);
        g_partial[row] = P * N / (yn * ybn);
        __threadfence();
        unsigned int done = atomicAdd(&g_count, 1u);
        is_last = (done == gridDim.x - 1);
    }
    __syncthreads();

    if (is_last) {
        // Final mean over 512 partials: 2 elements per thread, block reduce.
        float v = g_partial[tid] + g_partial[tid + TPB];
        #pragma unroll
        for (int o = 16; o > 0; o >>= 1)
            v += __shfl_down_sync(0xFFFFFFFFu, v, o);
        if (lane == 0) sp[warp] = v;
        __syncthreads();
        if (tid == 0) {
            float total = 0.0f;
            #pragma unroll
            for (int i = 0; i < TPB / 32; i++) total += sp[i];
            out[0] = total / (float)ROWS;
            g_count = 0;  // reset for graph replay
        }
    }
}

extern "C" void kernel_launch(void* const* d_in, const int* in_sizes, int n_in,
                              void* d_out, int out_size) {
    const float* c = (const float*)d_in[0];
    const int*   y = (const int*)d_in[1];
    float*       out = (float*)d_out;
    bpmll_kernel<<<ROWS, TPB>>>(c, y, out);
}

// round 2
// speedup vs baseline: 1.2798x; 1.2798x over previous
#include <cuda_runtime.h>
#include <cuda_bf16.h>

// BPMLL loss, MUFU-optimized:
//   pos_i = sum_{y=1} exp(-sigmoid(c)) = e^{-1} * sum_{y=1} h(-c)
//   neg_i = sum_{y=0} exp( sigmoid(c)) =          sum_{y=0} h( c)
//   where h(x) = exp(sigmoid(x)), computed as EX2 + RCP (sigmoid) followed by a
//   degree-4 minimax polynomial for exp(s), s in (0,1)  (max rel err ~2.7e-5).
//   out = mean_i( pos_i * neg_i / (|Y_i| * (512-|Y_i|)) )
//
// 512 blocks (one per row) x 128 threads, float4/int4 loads (4 elems/thread).
// Last-block finalize via threadfence + atomic counter (reset for graph replay).

#define ROWS 512
#define COLS 512
#define TPB  128

// exp(s) on [0,1], Chebyshev-economized degree 4 (coeffs in s-basis)
#define D0 1.00002694f
#define D1 0.99871530f
#define D2 0.50996560f
#define D3 0.13998530f
#define D4 0.06956140f
#define E_INV 0.36787944117144233f

__device__ float        g_partial[ROWS];
__device__ unsigned int g_count = 0;

__device__ __forceinline__ void elem(float c, int y,
                                     float& pos, float& neg, int& ys) {
    // x = y ? -c : c   (sign-bit XOR, ALU pipe)
    float x = __int_as_float(__float_as_int(c) ^ (y << 31));
    float t = __expf(-x);                  // FMUL + MUFU.EX2
    float d = 1.0f + t;
    float s;                               // sigmoid(x) = 1/(1+e^{-x})
    asm("rcp.approx.f32 %0, %1;" : "=f"(s) : "f"(d));   // MUFU.RCP
    // h = exp(s) via degree-4 poly (4 FMA)
    float h = fmaf(s, D4, D3);
    h = fmaf(h, s, D2);
    h = fmaf(h, s, D1);
    h = fmaf(h, s, D0);
    if (y) { pos += h; ys++; } else { neg += h; }
}

__global__ __launch_bounds__(TPB) void bpmll_kernel(const float* __restrict__ c,
                                                    const int*   __restrict__ y,
                                                    float* __restrict__ out) {
    const int row = blockIdx.x;
    const int tid = threadIdx.x;

    const float4 cv = reinterpret_cast<const float4*>(c + (size_t)row * COLS)[tid];
    const int4   yv = reinterpret_cast<const int4*>(y + (size_t)row * COLS)[tid];

    float pos = 0.0f, neg = 0.0f;
    int   ys  = 0;
    elem(cv.x, yv.x, pos, neg, ys);
    elem(cv.y, yv.y, pos, neg, ys);
    elem(cv.z, yv.z, pos, neg, ys);
    elem(cv.w, yv.w, pos, neg, ys);

    // Warp reduction
    #pragma unroll
    for (int o = 16; o > 0; o >>= 1) {
        pos += __shfl_down_sync(0xFFFFFFFFu, pos, o);
        neg += __shfl_down_sync(0xFFFFFFFFu, neg, o);
        ys  += __shfl_down_sync(0xFFFFFFFFu, ys,  o);
    }

    __shared__ float sp[TPB / 32];
    __shared__ float sn[TPB / 32];
    __shared__ int   sy[TPB / 32];
    const int lane = tid & 31, warp = tid >> 5;
    if (lane == 0) { sp[warp] = pos; sn[warp] = neg; sy[warp] = ys; }
    __syncthreads();

    __shared__ bool is_last;
    if (tid == 0) {
        float P = 0.0f, N = 0.0f; int Y = 0;
        #pragma unroll
        for (int i = 0; i < TPB / 32; i++) { P += sp[i]; N += sn[i]; Y += sy[i]; }
        const float yn  = (float)Y;
        const float ybn = (float)(COLS - Y);
        g_partial[row] = (E_INV * P) * N / (yn * ybn);
        __threadfence();
        unsigned int done = atomicAdd(&g_count, 1u);
        is_last = (done == gridDim.x - 1);
    }
    __syncthreads();

    if (is_last) {
        // Final mean over 512 partials: 4 per thread, block reduce.
        float v = g_partial[tid] + g_partial[tid + TPB]
                + g_partial[tid + 2 * TPB] + g_partial[tid + 3 * TPB];
        #pragma unroll
        for (int o = 16; o > 0; o >>= 1)
            v += __shfl_down_sync(0xFFFFFFFFu, v, o);
        if (lane == 0) sp[warp] = v;
        __syncthreads();
        if (tid == 0) {
            float total = 0.0f;
            #pragma unroll
            for (int i = 0; i < TPB / 32; i++) total += sp[i];
            out[0] = total / (float)ROWS;
            g_count = 0;  // reset for graph replay
        }
    }
}

extern "C" void kernel_launch(void* const* d_in, const int* in_sizes, int n_in,
                              void* d_out, int out_size) {
    const float* c = (const float*)d_in[0];
    const int*   y = (const int*)d_in[1];
    float*       out = (float*)d_out;
    bpmll_kernel<<<ROWS, TPB>>>(c, y, out);
}

// round 3
// speedup vs baseline: 1.2977x; 1.0140x over previous
#include <cuda_runtime.h>
#include <cuda_bf16.h>

// BPMLL loss, two-kernel (atomic-free) version:
//   Kernel A: one block per row -> g_partial[row] = pos*neg/(|Y|*(512-|Y|))
//   Kernel B: single block reduces the 512 partials -> out = mean
//
// Math per element (2 MUFU + 4 FMA):
//   exp(-sigmoid(c)) = e^{-1} * exp(sigmoid(-c)), so every element needs only
//   h(x) = exp(sigmoid(x)) with x = y ? -c : c.  sigmoid = EX2 + RCP;
//   exp(s), s in (0,1), via degree-4 Chebyshev-economized poly (rel err ~3e-5).

#define ROWS 512
#define COLS 512
#define TPB  128

#define D0 1.00002694f
#define D1 0.99871530f
#define D2 0.50996560f
#define D3 0.13998530f
#define D4 0.06956140f
#define E_INV 0.36787944117144233f

__device__ float g_partial[ROWS];

__device__ __forceinline__ void elem(float c, int y,
                                     float& pos, float& neg, int& ys) {
    float x = __int_as_float(__float_as_int(c) ^ (y << 31));  // y ? -c : c
    float t = __expf(-x);                                     // MUFU.EX2
    float d = 1.0f + t;
    float s;
    asm("rcp.approx.f32 %0, %1;" : "=f"(s) : "f"(d));         // MUFU.RCP
    float h = fmaf(s, D4, D3);
    h = fmaf(h, s, D2);
    h = fmaf(h, s, D1);
    h = fmaf(h, s, D0);
    if (y) { pos += h; ys++; } else { neg += h; }
}

__global__ __launch_bounds__(TPB) void bpmll_rows(const float* __restrict__ c,
                                                  const int*   __restrict__ y) {
    const int row = blockIdx.x;
    const int tid = threadIdx.x;

    const float4 cv = reinterpret_cast<const float4*>(c + (size_t)row * COLS)[tid];
    const int4   yv = reinterpret_cast<const int4*>(y + (size_t)row * COLS)[tid];

    float pos = 0.0f, neg = 0.0f;
    int   ys  = 0;
    elem(cv.x, yv.x, pos, neg, ys);
    elem(cv.y, yv.y, pos, neg, ys);
    elem(cv.z, yv.z, pos, neg, ys);
    elem(cv.w, yv.w, pos, neg, ys);

    #pragma unroll
    for (int o = 16; o > 0; o >>= 1) {
        pos += __shfl_down_sync(0xFFFFFFFFu, pos, o);
        neg += __shfl_down_sync(0xFFFFFFFFu, neg, o);
        ys  += __shfl_down_sync(0xFFFFFFFFu, ys,  o);
    }

    __shared__ float sp[TPB / 32];
    __shared__ float sn[TPB / 32];
    __shared__ int   sy[TPB / 32];
    const int lane = tid & 31, warp = tid >> 5;
    if (lane == 0) { sp[warp] = pos; sn[warp] = neg; sy[warp] = ys; }
    __syncthreads();

    if (tid == 0) {
        float P = 0.0f, N = 0.0f; int Y = 0;
        #pragma unroll
        for (int i = 0; i < TPB / 32; i++) { P += sp[i]; N += sn[i]; Y += sy[i]; }
        const float yn  = (float)Y;
        const float ybn = (float)(COLS - Y);
        g_partial[row] = (E_INV * P) * N / (yn * ybn);
    }
}

__global__ __launch_bounds__(512) void bpmll_finalize(float* __restrict__ out) {
    const int tid = threadIdx.x;
    float v = g_partial[tid];

    #pragma unroll
    for (int o = 16; o > 0; o >>= 1)
        v += __shfl_down_sync(0xFFFFFFFFu, v, o);

    __shared__ float sp[16];
    const int lane = tid & 31, warp = tid >> 5;
    if (lane == 0) sp[warp] = v;
    __syncthreads();

    if (tid == 0) {
        float total = 0.0f;
        #pragma unroll
        for (int i = 0; i < 16; i++) total += sp[i];
        out[0] = total / (float)ROWS;
    }
}

extern "C" void kernel_launch(void* const* d_in, const int* in_sizes, int n_in,
                              void* d_out, int out_size) {
    const float* c = (const float*)d_in[0];
    const int*   y = (const int*)d_in[1];
    float*       out = (float*)d_out;
    bpmll_rows<<<ROWS, TPB>>>(c, y);
    bpmll_finalize<<<1, 512>>>(out);
}

// round 4
// speedup vs baseline: 1.3413x; 1.0337x over previous
#include <cuda_runtime.h>
#include <cuda_bf16.h>

// BPMLL loss, single launch, fence-free last-block finalize:
//   - per-row partial stored with st.global.cg (L2-visible, no L1 flush)
//   - completion counter via atom.acq_rel.gpu.add (release orders the store,
//     acquire on the winning block orders its subsequent partial reads)
//   - NO __threadfence: GPU-scope fence emits CCTL.IVALL (full L1D flush) on
//     sm_103a, which was serializing co-resident blocks in earlier rounds.
//
// Math per element (2 MUFU + 4 FMA):
//   exp(-sigmoid(c)) = e^{-1} * exp(sigmoid(-c)) -> only h(x)=exp(sigmoid(x))
//   with x = y ? -c : c. sigmoid = EX2 + RCP; exp(s), s in (0,1), via a
//   degree-4 Chebyshev-economized polynomial (rel err ~3e-5).

#define ROWS 512
#define COLS 512
#define TPB  128

#define D0 1.00002694f
#define D1 0.99871530f
#define D2 0.50996560f
#define D3 0.13998530f
#define D4 0.06956140f
#define E_INV 0.36787944117144233f

__device__ float        g_partial[ROWS];
__device__ unsigned int g_count = 0;

__device__ __forceinline__ void elem(float c, int y,
                                     float& pos, float& neg, int& ys) {
    float x = __int_as_float(__float_as_int(c) ^ (y << 31));  // y ? -c : c
    float t = __expf(-x);                                     // MUFU.EX2
    float d = 1.0f + t;
    float s;
    asm("rcp.approx.f32 %0, %1;" : "=f"(s) : "f"(d));         // MUFU.RCP
    float h = fmaf(s, D4, D3);
    h = fmaf(h, s, D2);
    h = fmaf(h, s, D1);
    h = fmaf(h, s, D0);
    if (y) { pos += h; ys++; } else { neg += h; }
}

__global__ __launch_bounds__(TPB) void bpmll_kernel(const float* __restrict__ c,
                                                    const int*   __restrict__ y,
                                                    float* __restrict__ out) {
    const int row = blockIdx.x;
    const int tid = threadIdx.x;

    const float4 cv = reinterpret_cast<const float4*>(c + (size_t)row * COLS)[tid];
    const int4   yv = reinterpret_cast<const int4*>(y + (size_t)row * COLS)[tid];

    float pos = 0.0f, neg = 0.0f;
    int   ys  = 0;
    elem(cv.x, yv.x, pos, neg, ys);
    elem(cv.y, yv.y, pos, neg, ys);
    elem(cv.z, yv.z, pos, neg, ys);
    elem(cv.w, yv.w, pos, neg, ys);

    #pragma unroll
    for (int o = 16; o > 0; o >>= 1) {
        pos += __shfl_down_sync(0xFFFFFFFFu, pos, o);
        neg += __shfl_down_sync(0xFFFFFFFFu, neg, o);
        ys  += __shfl_down_sync(0xFFFFFFFFu, ys,  o);
    }

    __shared__ float sp[TPB / 32];
    __shared__ float sn[TPB / 32];
    __shared__ int   sy[TPB / 32];
    const int lane = tid & 31, warp = tid >> 5;
    if (lane == 0) { sp[warp] = pos; sn[warp] = neg; sy[warp] = ys; }
    __syncthreads();

    __shared__ bool is_last;
    if (tid == 0) {
        float P = 0.0f, N = 0.0f; int Y = 0;
        #pragma unroll
        for (int i = 0; i < TPB / 32; i++) { P += sp[i]; N += sn[i]; Y += sy[i]; }
        const float yn  = (float)Y;
        const float ybn = (float)(COLS - Y);
        float part = (E_INV * P) * N / (yn * ybn);

        // L2-visible store of the partial (no L1 involvement)
        asm volatile("st.global.cg.f32 [%0], %1;"
                     :: "l"(&g_partial[row]), "f"(part) : "memory");
        // release-ordered counter increment; acquire on the return path
        unsigned int old;
        asm volatile("atom.acq_rel.gpu.global.add.u32 %0, [%1], %2;"
                     : "=r"(old) : "l"(&g_count), "r"(1u) : "memory");
        is_last = (old == (unsigned)(ROWS - 1));
    }
    __syncthreads();

    if (is_last) {
        // 4 partials per thread, read through L2 (.cg) to bypass stale L1.
        float v;
        {
            float a, b, e, f;
            asm volatile("ld.global.cg.f32 %0, [%1];" : "=f"(a) : "l"(&g_partial[tid]));
            asm volatile("ld.global.cg.f32 %0, [%1];" : "=f"(b) : "l"(&g_partial[tid + TPB]));
            asm volatile("ld.global.cg.f32 %0, [%1];" : "=f"(e) : "l"(&g_partial[tid + 2 * TPB]));
            asm volatile("ld.global.cg.f32 %0, [%1];" : "=f"(f) : "l"(&g_partial[tid + 3 * TPB]));
            v = (a + b) + (e + f);
        }
        #pragma unroll
        for (int o = 16; o > 0; o >>= 1)
            v += __shfl_down_sync(0xFFFFFFFFu, v, o);
        if (lane == 0) sp[warp] = v;
        __syncthreads();
        if (tid == 0) {
            float total = 0.0f;
            #pragma unroll
            for (int i = 0; i < TPB / 32; i++) total += sp[i];
            out[0] = total / (float)ROWS;
            // reset counter for next graph replay (kernel boundary orders this)
            asm volatile("st.global.cg.u32 [%0], %1;"
                         :: "l"(&g_count), "r"(0u) : "memory");
        }
    }
}

extern "C" void kernel_launch(void* const* d_in, const int* in_sizes, int n_in,
                              void* d_out, int out_size) {
    const float* c = (const float*)d_in[0];
    const int*   y = (const int*)d_in[1];
    float*       out = (float*)d_out;
    bpmll_kernel<<<ROWS, TPB>>>(c, y, out);
}